// round 4
// baseline (speedup 1.0000x reference)
#include <cuda_runtime.h>

// SeqSelfAttention (Bahdanau additive, windowed) — GB300 sm_103a
// B=4, L=1024, D=128, U=32, WIDTH=64, EPS=1e-7
//
// Algebra: window-max softmax shift only perturbs the +1e-7 denominator by
// exp(Mw-Mfull) (rel err <~1e-6); ba cancels exactly.
// R4: 1 query/warp x 8 warps (2x occupancy), float4 kb loads, packed
// fma.rn.f32x2 in AV + add.rn.f32x2 in logits, transposed-W qk kernel.

#define LSEQ 1024
#define BB   4
#define DD   128
#define UU   32
#define TI   8
#define CW   72
#define NROWS (BB*LSEQ)

typedef unsigned long long u64;

__device__ float g_q [NROWS*UU];
__device__ float g_kb[NROWS*UU];

__device__ __forceinline__ float fast_tanh(float x){
    float y; asm("tanh.approx.f32 %0, %1;" : "=f"(y) : "f"(x)); return y;
}
__device__ __forceinline__ void fma2(u64& d, u64 a, u64 b){
    asm("fma.rn.f32x2 %0, %1, %2, %0;" : "+l"(d) : "l"(a), "l"(b));
}
__device__ __forceinline__ u64 add2(u64 a, u64 b){
    u64 d; asm("add.rn.f32x2 %0, %1, %2;" : "=l"(d) : "l"(a), "l"(b)); return d;
}
__device__ __forceinline__ u64 pack2(float lo, float hi){
    u64 d;
    asm("mov.b64 %0, {%1, %2};" : "=l"(d)
        : "r"(__float_as_uint(lo)), "r"(__float_as_uint(hi)));
    return d;
}
__device__ __forceinline__ void unpack2(u64 v, float& lo, float& hi){
    unsigned a, b;
    asm("mov.b64 {%0, %1}, %2;" : "=r"(a), "=r"(b) : "l"(v));
    lo = __uint_as_float(a); hi = __uint_as_float(b);
}

// ---------------------------------------------------------------------------
// Kernel 1: q = x @ Wt ; kb = x @ Wx + bh.  256 blocks x 256 thr, 2 rows/warp.
// W transposed in smem: wts[u][d], stride 132 (conflict-free LDS.128).
// ---------------------------------------------------------------------------
#define QK_RPB 16
#define WTS 132
__global__ __launch_bounds__(256) void qk_kernel(
        const float* __restrict__ x,
        const float* __restrict__ Wt,
        const float* __restrict__ Wx,
        const float* __restrict__ bh)
{
    __shared__ float xs [QK_RPB*DD];    // 8 KB
    __shared__ float wts[UU*WTS];       // 16.5 KB (transposed)
    __shared__ float wxs[UU*WTS];
    const int t    = threadIdx.x;
    const int row0 = blockIdx.x * QK_RPB;

    {   // stage x (coalesced float4) and W (transposed scalar)
        const float4* xg = (const float4*)(x + row0*DD);
        float4* xs4 = (float4*)xs;
        xs4[t] = xg[t];  xs4[t+256] = xg[t+256];
        #pragma unroll
        for (int i = 0; i < 16; i++){
            const int idx = t + i*256;          // 4096 elements of [128][32]
            const int d = idx >> 5, u = idx & 31;
            wts[u*WTS + d] = Wt[idx];
            wxs[u*WTS + d] = Wx[idx];
        }
    }
    __syncthreads();

    const int u  = t & 31;
    const int rg = t >> 5;                // warp -> rows r0, r0+1
    const int r0 = rg*2;
    const ulonglong2* wtp = (const ulonglong2*)(wts + u*WTS);
    const ulonglong2* wxp = (const ulonglong2*)(wxs + u*WTS);
    const ulonglong2* x0p = (const ulonglong2*)(xs + r0*DD);
    const ulonglong2* x1p = x0p + 32;

    u64 aq0A=0,aq0B=0,aq1A=0,aq1B=0, ak0A=0,ak0B=0,ak1A=0,ak1B=0;
    #pragma unroll 8
    for (int d4 = 0; d4 < 32; d4++){
        const ulonglong2 wt = wtp[d4];
        const ulonglong2 wx = wxp[d4];
        const ulonglong2 x0 = x0p[d4];     // broadcast
        const ulonglong2 x1 = x1p[d4];     // broadcast
        fma2(aq0A, x0.x, wt.x); fma2(aq0B, x0.y, wt.y);
        fma2(aq1A, x1.x, wt.x); fma2(aq1B, x1.y, wt.y);
        fma2(ak0A, x0.x, wx.x); fma2(ak0B, x0.y, wx.y);
        fma2(ak1A, x1.x, wx.x); fma2(ak1B, x1.y, wx.y);
    }
    float lo, hi, s0, s1, s2, s3;
    unpack2(add2(aq0A, aq0B), lo, hi); s0 = lo + hi;
    unpack2(add2(aq1A, aq1B), lo, hi); s1 = lo + hi;
    unpack2(add2(ak0A, ak0B), lo, hi); s2 = lo + hi;
    unpack2(add2(ak1A, ak1B), lo, hi); s3 = lo + hi;
    const float bhv = bh[u];
    const int r = row0 + r0;
    g_q [(r+0)*UU+u] = s0;       g_q [(r+1)*UU+u] = s1;
    g_kb[(r+0)*UU+u] = s2+bhv;   g_kb[(r+1)*UU+u] = s3+bhv;
}

// ---------------------------------------------------------------------------
// Kernel 2: windowed attention. grid (L/TI, B), 256 threads (8 warps).
// Warp w owns query i0+w; lane l owns keys c0=w+l, c1=w+l+32.
// smem: xs[72][128] | kbs[72][36] | qs[8][32] | was[32] | Aw[8][68]
// ---------------------------------------------------------------------------
#define KBS  36
#define OFF_KBS  (CW*DD)                   // 9216
#define OFF_QS   (OFF_KBS + CW*KBS)        // 11808
#define OFF_WAS  (OFF_QS + TI*UU)          // 12064
#define OFF_AW   (OFF_WAS + UU)            // 12096
#define SMEM_FLOATS (OFF_AW + TI*68)       // 12640 floats = 50560 B

extern __shared__ float smem[];

__global__ __launch_bounds__(256) void attn_kernel(
        const float* __restrict__ x,
        const float* __restrict__ Wa,
        float* __restrict__ out)
{
    float* xs  = smem;
    float* kbs = smem + OFF_KBS;
    float* qs  = smem + OFF_QS;
    float* was = smem + OFF_WAS;
    float* Aw  = smem + OFF_AW;

    const int t    = threadIdx.x;
    const int i0   = blockIdx.x * TI;
    const int base = blockIdx.y * LSEQ;

    // ---- stage: xs[72][128] f4, kbs[72][36] f4, qs, was ----
    {
        float4* xs4 = (float4*)xs;
        const float4* xg4 = (const float4*)x;
        #pragma unroll
        for (int i = 0; i < 9; i++){
            const int idx = t + i*256;            // [0,2304) f4 of [72][32]
            const int c = idx >> 5, dq = idx & 31;
            const int j = i0 - 32 + c;
            float4 v = make_float4(0.f,0.f,0.f,0.f);
            if (j >= 0 && j < LSEQ) v = xg4[(base + j)*32 + dq];
            xs4[c*32 + dq] = v;
        }
        const float4* kg4 = (const float4*)g_kb;
        #pragma unroll
        for (int i = 0; i < 3; i++){
            const int idx = t + i*256;            // [0,576) f4 of [72][8]
            if (idx < 576){
                const int c = idx >> 3, u4 = idx & 7;
                const int j = i0 - 32 + c;
                float4 v = make_float4(0.f,0.f,0.f,0.f);
                if (j >= 0 && j < LSEQ) v = kg4[(base + j)*8 + u4];
                ((float4*)(kbs + c*KBS))[u4] = v;
            }
        }
        if (t < 64) ((float4*)qs)[t] = ((const float4*)(g_q + (base+i0)*UU))[t];
        if (t < 32) was[t] = Wa[t];
    }
    __syncthreads();

    const int w = t >> 5;
    const int l = t & 31;
    const int c0 = w + l, c1 = c0 + 32;

    // ---- logits: e = sum_u Wa_u * tanh(q_u + kb_u) (packed adds) ----
    float e0 = 0.f, e1 = 0.f;
    {
        const ulonglong2* qp  = (const ulonglong2*)(qs + w*UU);
        const ulonglong2* kp0 = (const ulonglong2*)(kbs + c0*KBS);
        const ulonglong2* kp1 = (const ulonglong2*)(kbs + c1*KBS);
        const float4* wap = (const float4*)was;
        #pragma unroll
        for (int u4 = 0; u4 < 8; u4++){
            const ulonglong2 qq = qp[u4];         // broadcast LDS.128
            const ulonglong2 k0 = kp0[u4];        // conflict-free LDS.128
            const ulonglong2 k1 = kp1[u4];
            const float4 wa4 = wap[u4];           // broadcast
            float a,b,c,d, p,q2,r,s;
            unpack2(add2(qq.x, k0.x), a, b);
            unpack2(add2(qq.y, k0.y), c, d);
            unpack2(add2(qq.x, k1.x), p, q2);
            unpack2(add2(qq.y, k1.y), r, s);
            e0 += wa4.x*fast_tanh(a) + wa4.y*fast_tanh(b)
                + wa4.z*fast_tanh(c) + wa4.w*fast_tanh(d);
            e1 += wa4.x*fast_tanh(p) + wa4.y*fast_tanh(q2)
                + wa4.z*fast_tanh(r) + wa4.w*fast_tanh(s);
        }
        const int j0 = i0 - 32 + c0;
        if (j0 < 0)            e0 = -1e30f;
        if (j0 + 32 >= LSEQ)   e1 = -1e30f;
    }

    // ---- warp softmax (registers only) ----
    float a0, a1;
    {
        float m = fmaxf(e0, e1);
        #pragma unroll
        for (int o = 16; o; o >>= 1) m = fmaxf(m, __shfl_xor_sync(0xffffffffu, m, o));
        const float w0 = __expf(e0 - m);
        const float w1 = __expf(e1 - m);
        float s = w0 + w1;
        #pragma unroll
        for (int o = 16; o; o >>= 1) s += __shfl_xor_sync(0xffffffffu, s, o);
        const float inv = 1.f / (s + 1e-7f);
        a0 = w0 * inv; a1 = w1 * inv;
    }

    // ---- publish weights (warp-private slab), then AV with f32x2 ----
    float* A = Aw + w*68;
    A[l] = a0; A[l+32] = a1;
    __syncwarp();

    {
        const float4* Ar = (const float4*)A;
        u64 accAlo=0, accAhi=0, accBlo=0, accBhi=0;   // two chains
        #pragma unroll
        for (int k4 = 0; k4 < 16; k4++){
            const float4 a4 = Ar[k4];                 // broadcast LDS.128
            const ulonglong2* xp =
                (const ulonglong2*)(xs + (w + k4*4)*DD) + l;
            ulonglong2 xv;
            u64 aa;
            xv = xp[0];   aa = pack2(a4.x, a4.x);
            fma2(accAlo, aa, xv.x); fma2(accAhi, aa, xv.y);
            xv = xp[32];  aa = pack2(a4.y, a4.y);
            fma2(accBlo, aa, xv.x); fma2(accBhi, aa, xv.y);
            xv = xp[64];  aa = pack2(a4.z, a4.z);
            fma2(accAlo, aa, xv.x); fma2(accAhi, aa, xv.y);
            xv = xp[96];  aa = pack2(a4.w, a4.w);
            fma2(accBlo, aa, xv.x); fma2(accBhi, aa, xv.y);
        }
        float4 r;
        unpack2(add2(accAlo, accBlo), r.x, r.y);
        unpack2(add2(accAhi, accBhi), r.z, r.w);
        ((float4*)out)[(base + i0 + w)*32 + l] = r;
    }
}

// ---------------------------------------------------------------------------
extern "C" void kernel_launch(void* const* d_in, const int* in_sizes, int n_in,
                              void* d_out, int out_size)
{
    const float* x  = (const float*)d_in[0];
    const float* Wt = (const float*)d_in[1];
    const float* Wx = (const float*)d_in[2];
    const float* bh = (const float*)d_in[3];
    const float* Wa = (const float*)d_in[4];
    // d_in[5] = ba : cancels exactly in the shifted softmax -> unused
    float* out = (float*)d_out;

    qk_kernel<<<NROWS/QK_RPB, 256>>>(x, Wt, Wx, bh);

    cudaFuncSetAttribute(attn_kernel,
                         cudaFuncAttributeMaxDynamicSharedMemorySize,
                         SMEM_FLOATS*4 + 256);
    dim3 grid(LSEQ/TI, BB);
    attn_kernel<<<grid, 256, SMEM_FLOATS*4>>>(x, Wa, out);
}

// round 5
// speedup vs baseline: 1.2765x; 1.2765x over previous
#include <cuda_runtime.h>

// SeqSelfAttention (Bahdanau additive, windowed) — GB300 sm_103a
// B=4, L=1024, D=128, U=32, WIDTH=64, EPS=1e-7
//
// Algebra: window-max softmax shift only perturbs the +1e-7 denominator by
// exp(Mw-Mfull) (rel err <~1e-6); ba cancels exactly.
// R5: TI=16 tile (44% less staging/query, 2x occupancy vs R3), R3-style
// 2 queries/warp with shared xv reads, scalar fp32 math, float4 kb loads.
// qk: 4 rows/warp, 32 rows/block (halved W smem re-reads).

#define LSEQ 1024
#define BB   4
#define DD   128
#define UU   32
#define TI   16
#define CW   80   // TI + 64
#define NROWS (BB*LSEQ)

__device__ float g_q [NROWS*UU];
__device__ float g_kb[NROWS*UU];

__device__ __forceinline__ float fast_tanh(float x){
    float y; asm("tanh.approx.f32 %0, %1;" : "=f"(y) : "f"(x)); return y;
}

// ---------------------------------------------------------------------------
// Kernel 1: q = x @ Wt ; kb = x @ Wx + bh.  128 blocks x 256 thr, 32 rows,
// 4 rows/warp. W in natural [d][u] layout (f4-coalesced stage, conflict-free
// scalar reads: lane = u).
// ---------------------------------------------------------------------------
#define QK_RPB 32
__global__ __launch_bounds__(256) void qk_kernel(
        const float* __restrict__ x,
        const float* __restrict__ Wt,
        const float* __restrict__ Wx,
        const float* __restrict__ bh)
{
    __shared__ float xs [QK_RPB*DD];    // 16 KB
    __shared__ float wts[DD*UU];        // 16 KB  [d][u]
    __shared__ float wxs[DD*UU];        // 16 KB
    const int t    = threadIdx.x;
    const int row0 = blockIdx.x * QK_RPB;

    {   // stage (all coalesced float4, layout-preserving)
        const float4* xg = (const float4*)(x + row0*DD);
        float4* xs4 = (float4*)xs;
        const float4* wtg = (const float4*)Wt; float4* wt4 = (float4*)wts;
        const float4* wxg = (const float4*)Wx; float4* wx4 = (float4*)wxs;
        #pragma unroll
        for (int i = 0; i < 4; i++){
            xs4[t + i*256] = xg [t + i*256];
            wt4[t + i*256] = wtg[t + i*256];
            wx4[t + i*256] = wxg[t + i*256];
        }
    }
    __syncthreads();

    const int u  = t & 31;
    const int rg = t >> 5;
    const int rb = rg * 4;                 // 4 rows per warp
    float aq0=0,aq1=0,aq2=0,aq3=0, ak0=0,ak1=0,ak2=0,ak3=0;
    const float4* xs4 = (const float4*)xs;

    #pragma unroll 8
    for (int d4 = 0; d4 < 32; d4++){
        const int db = d4*4*32 + u;
        const float wt0 = wts[db], wt1 = wts[db+32], wt2 = wts[db+64], wt3 = wts[db+96];
        const float wx0 = wxs[db], wx1 = wxs[db+32], wx2 = wxs[db+64], wx3 = wxs[db+96];
        const float4 x0 = xs4[(rb+0)*32 + d4];   // broadcast LDS.128
        const float4 x1 = xs4[(rb+1)*32 + d4];
        const float4 x2 = xs4[(rb+2)*32 + d4];
        const float4 x3 = xs4[(rb+3)*32 + d4];
        aq0 += x0.x*wt0 + x0.y*wt1 + x0.z*wt2 + x0.w*wt3;
        aq1 += x1.x*wt0 + x1.y*wt1 + x1.z*wt2 + x1.w*wt3;
        aq2 += x2.x*wt0 + x2.y*wt1 + x2.z*wt2 + x2.w*wt3;
        aq3 += x3.x*wt0 + x3.y*wt1 + x3.z*wt2 + x3.w*wt3;
        ak0 += x0.x*wx0 + x0.y*wx1 + x0.z*wx2 + x0.w*wx3;
        ak1 += x1.x*wx0 + x1.y*wx1 + x1.z*wx2 + x1.w*wx3;
        ak2 += x2.x*wx0 + x2.y*wx1 + x2.z*wx2 + x2.w*wx3;
        ak3 += x3.x*wx0 + x3.y*wx1 + x3.z*wx2 + x3.w*wx3;
    }
    const float bhv = bh[u];
    const int r = row0 + rb;
    g_q [(r+0)*UU+u] = aq0;      g_q [(r+1)*UU+u] = aq1;
    g_q [(r+2)*UU+u] = aq2;      g_q [(r+3)*UU+u] = aq3;
    g_kb[(r+0)*UU+u] = ak0+bhv;  g_kb[(r+1)*UU+u] = ak1+bhv;
    g_kb[(r+2)*UU+u] = ak2+bhv;  g_kb[(r+3)*UU+u] = ak3+bhv;
}

// ---------------------------------------------------------------------------
// Kernel 2: windowed attention. grid (L/16, B) = 256 blocks, 256 thr.
// Warp w owns queries 2w, 2w+1; lane l -> q0 keys c0=2w+l, c1=c0+32;
// q1 keys c0+1, c1+1. xv reads shared across the two queries in AV.
// smem: xs[80][128] | kbs[80][36] | qs[16][32] | was[32] | Aw[8][132]
// ---------------------------------------------------------------------------
#define KBS  36
#define OFF_KBS  (CW*DD)                   // 10240
#define OFF_QS   (OFF_KBS + CW*KBS)        // 13120
#define OFF_WAS  (OFF_QS + TI*UU)          // 13632
#define OFF_AW   (OFF_WAS + UU)            // 13664
#define SMEM_FLOATS (OFF_AW + 8*132)       // 14720 floats = 58880 B

extern __shared__ float smem[];

__global__ __launch_bounds__(256) void attn_kernel(
        const float* __restrict__ x,
        const float* __restrict__ Wa,
        float* __restrict__ out)
{
    float* xs  = smem;
    float* kbs = smem + OFF_KBS;
    float* qs  = smem + OFF_QS;
    float* was = smem + OFF_WAS;
    float* Aw  = smem + OFF_AW;

    const int t    = threadIdx.x;
    const int i0   = blockIdx.x * TI;
    const int base = blockIdx.y * LSEQ;

    // ---- stage: xs[80][128] f4, kbs[80][36] f4, qs[16][32], was ----
    {
        float4* xs4 = (float4*)xs;
        const float4* xg4 = (const float4*)x;
        #pragma unroll
        for (int i = 0; i < 10; i++){
            const int idx = t + i*256;            // [0,2560) f4 of [80][32]
            const int c = idx >> 5, dq = idx & 31;
            const int j = i0 - 32 + c;
            float4 v = make_float4(0.f,0.f,0.f,0.f);
            if (j >= 0 && j < LSEQ) v = xg4[(base + j)*32 + dq];
            xs4[c*32 + dq] = v;
        }
        const float4* kg4 = (const float4*)g_kb;
        #pragma unroll
        for (int i = 0; i < 3; i++){
            const int idx = t + i*256;            // [0,640) f4 of [80][8]
            if (idx < 640){
                const int c = idx >> 3, u4 = idx & 7;
                const int j = i0 - 32 + c;
                float4 v = make_float4(0.f,0.f,0.f,0.f);
                if (j >= 0 && j < LSEQ) v = kg4[(base + j)*8 + u4];
                ((float4*)(kbs + c*KBS))[u4] = v;
            }
        }
        if (t < 128) ((float4*)qs)[t] = ((const float4*)(g_q + (base+i0)*UU))[t];
        if (t < 32) was[t] = Wa[t];
    }
    __syncthreads();

    const int w = t >> 5;
    const int l = t & 31;
    const int c0 = 2*w + l, c1 = c0 + 32;

    // ---- logits: 4 series, float4 kb (stride-36: conflict-free LDS.128) ----
    float e00 = 0.f, e01 = 0.f, e10 = 0.f, e11 = 0.f;
    {
        const float4* q0p = (const float4*)(qs + 2*w*UU);
        const float4* q1p = q0p + 8;
        const float4* kAp = (const float4*)(kbs + c0*KBS);
        const float4* kBp = (const float4*)(kbs + c1*KBS);
        const float4* kCp = (const float4*)(kbs + (c0+1)*KBS);
        const float4* kDp = (const float4*)(kbs + (c1+1)*KBS);
        const float4* wap = (const float4*)was;
        #pragma unroll
        for (int u4 = 0; u4 < 8; u4++){
            const float4 wa = wap[u4];            // broadcast
            const float4 q0 = q0p[u4];            // broadcast
            const float4 q1 = q1p[u4];
            const float4 kA = kAp[u4];            // conflict-free
            const float4 kB = kBp[u4];
            const float4 kC = kCp[u4];
            const float4 kD = kDp[u4];
            e00 += wa.x*fast_tanh(q0.x+kA.x) + wa.y*fast_tanh(q0.y+kA.y)
                 + wa.z*fast_tanh(q0.z+kA.z) + wa.w*fast_tanh(q0.w+kA.w);
            e01 += wa.x*fast_tanh(q0.x+kB.x) + wa.y*fast_tanh(q0.y+kB.y)
                 + wa.z*fast_tanh(q0.z+kB.z) + wa.w*fast_tanh(q0.w+kB.w);
            e10 += wa.x*fast_tanh(q1.x+kC.x) + wa.y*fast_tanh(q1.y+kC.y)
                 + wa.z*fast_tanh(q1.z+kC.z) + wa.w*fast_tanh(q1.w+kC.w);
            e11 += wa.x*fast_tanh(q1.x+kD.x) + wa.y*fast_tanh(q1.y+kD.y)
                 + wa.z*fast_tanh(q1.z+kD.z) + wa.w*fast_tanh(q1.w+kD.w);
        }
    }
    {
        const int j0 = i0 - 32 + c0;              // key of e00
        if (j0 < 0)              e00 = -1e30f;
        if (j0 + 32 >= LSEQ)     e01 = -1e30f;
        if (j0 + 1 < 0)          e10 = -1e30f;
        if (j0 + 33 >= LSEQ)     e11 = -1e30f;
    }

    // ---- two warp softmaxes (registers only) ----
    float a00, a01, a10, a11;
    {
        float m0 = fmaxf(e00, e01), m1 = fmaxf(e10, e11);
        #pragma unroll
        for (int o = 16; o; o >>= 1){
            m0 = fmaxf(m0, __shfl_xor_sync(0xffffffffu, m0, o));
            m1 = fmaxf(m1, __shfl_xor_sync(0xffffffffu, m1, o));
        }
        const float w00 = __expf(e00 - m0), w01 = __expf(e01 - m0);
        const float w10 = __expf(e10 - m1), w11 = __expf(e11 - m1);
        float s0 = w00 + w01, s1 = w10 + w11;
        #pragma unroll
        for (int o = 16; o; o >>= 1){
            s0 += __shfl_xor_sync(0xffffffffu, s0, o);
            s1 += __shfl_xor_sync(0xffffffffu, s1, o);
        }
        const float inv0 = 1.f / (s0 + 1e-7f);
        const float inv1 = 1.f / (s1 + 1e-7f);
        a00 = w00*inv0; a01 = w01*inv0; a10 = w10*inv1; a11 = w11*inv1;
    }

    // ---- publish: slot k <-> key c = 2w+k ; .x = q0, .y = q1 ----
    float* A = Aw + w*132;
    A[2*l]          = a00;       // q0 slot l
    A[2*(l+1) + 1]  = a10;       // q1 slot l+1
    A[2*(l+32)]     = a01;       // q0 slot l+32
    A[2*(l+33) + 1] = a11;       // q1 slot l+33
    if (l == 0){ A[2*64] = 0.f; A[1] = 0.f; }   // q0@64, q1@0 unused
    __syncwarp();

    // ---- AV: one xv read feeds both queries ----
    {
        const float4* xs4 = (const float4*)xs;
        const float2* A2  = (const float2*)A;
        float4 acc0 = make_float4(0.f,0.f,0.f,0.f);
        float4 acc1 = make_float4(0.f,0.f,0.f,0.f);
        #pragma unroll 13
        for (int k = 0; k <= 64; k++){
            const float2 ab = A2[k];                 // broadcast LDS.64
            const float4 xv = xs4[(2*w + k)*32 + l]; // conflict-free LDS.128
            acc0.x += ab.x*xv.x; acc0.y += ab.x*xv.y;
            acc0.z += ab.x*xv.z; acc0.w += ab.x*xv.w;
            acc1.x += ab.y*xv.x; acc1.y += ab.y*xv.y;
            acc1.z += ab.y*xv.z; acc1.w += ab.y*xv.w;
        }
        float4* out4 = (float4*)out;
        out4[(base + i0 + 2*w    )*32 + l] = acc0;
        out4[(base + i0 + 2*w + 1)*32 + l] = acc1;
    }
}

// ---------------------------------------------------------------------------
extern "C" void kernel_launch(void* const* d_in, const int* in_sizes, int n_in,
                              void* d_out, int out_size)
{
    const float* x  = (const float*)d_in[0];
    const float* Wt = (const float*)d_in[1];
    const float* Wx = (const float*)d_in[2];
    const float* bh = (const float*)d_in[3];
    const float* Wa = (const float*)d_in[4];
    // d_in[5] = ba : cancels exactly in the shifted softmax -> unused
    float* out = (float*)d_out;

    qk_kernel<<<NROWS/QK_RPB, 256>>>(x, Wt, Wx, bh);

    cudaFuncSetAttribute(attn_kernel,
                         cudaFuncAttributeMaxDynamicSharedMemorySize,
                         SMEM_FLOATS*4 + 256);
    dim3 grid(LSEQ/TI, BB);
    attn_kernel<<<grid, 256, SMEM_FLOATS*4>>>(x, Wa, out);
}